// round 14
// baseline (speedup 1.0000x reference)
#include <cuda_runtime.h>
#include <cuda_fp16.h>
#include <cstdint>

// ---------------- problem constants ----------------
#define BB 64
#define CC 256
#define DD 128
#define NN 64
#define HH 256
#define SCALE_V 0.08838834764831845f   // 1/sqrt(128)

// ---------------- device scratch ----------------
__device__ float g_farr[BB][DD][NN];     // f_arr (fp32, exact cv path)
__device__ float g_cv[BB][NN];           // c[b][k]
// fp16 images
__device__ __align__(16) __half g_ft[2][BB][NN][DD];    // f_src/f_dst transposed
__device__ __align__(16) __half g_w1h[HH][HH];          // w1 fp16 [h][2d]
__device__ __align__(16) __half g_w3t[DD * DD];         // w3^T fp16 [o][p]
__device__ __align__(16) __half g_srcp_h[BB][NN][HH];   // src_p (+b1), fp16
__device__ __align__(16) __half g_dstp_h[BB][NN][HH];   // dst_p, fp16
__device__ __align__(16) __half g_w2h[32768];           // [o(128)][h(256)]
__device__ __align__(16) __half g_Gh[BB * 8192];        // [b][k_out(64)][o(128)]

// ---------------- helpers ----------------
__device__ __forceinline__ uint32_t smem_u32(const void* p) {
    uint32_t a;
    asm("{ .reg .u64 t; cvta.to.shared.u64 t, %1; cvt.u32.u64 %0, t; }" : "=r"(a) : "l"(p));
    return a;
}
__device__ __forceinline__ void ldmx4(uint32_t r[4], uint32_t addr) {
    asm volatile("ldmatrix.sync.aligned.m8n8.x4.shared.b16 {%0,%1,%2,%3}, [%4];"
                 : "=r"(r[0]), "=r"(r[1]), "=r"(r[2]), "=r"(r[3]) : "r"(addr));
}
__device__ __forceinline__ void mma16816(float c[4], const uint32_t a[4],
                                         uint32_t b0, uint32_t b1) {
    asm volatile(
        "mma.sync.aligned.m16n8k16.row.col.f32.f16.f16.f32 "
        "{%0,%1,%2,%3}, {%4,%5,%6,%7}, {%8,%9}, {%0,%1,%2,%3};"
        : "+f"(c[0]), "+f"(c[1]), "+f"(c[2]), "+f"(c[3])
        : "r"(a[0]), "r"(a[1]), "r"(a[2]), "r"(a[3]), "r"(b0), "r"(b1));
}
__device__ __forceinline__ uint32_t packh2(float x, float y) {
    __half2 h = __floats2half2_rn(x, y);
    return *reinterpret_cast<uint32_t*>(&h);
}
__device__ __forceinline__ uint4 reluadd4(uint4 s, uint4 d) {
    const __half2 zz = __floats2half2_rn(0.f, 0.f);
    const __half2* sh2 = reinterpret_cast<const __half2*>(&s);
    const __half2* dh2 = reinterpret_cast<const __half2*>(&d);
    __half2 t0 = __hmax2(__hadd2(sh2[0], dh2[0]), zz);
    __half2 t1 = __hmax2(__hadd2(sh2[1], dh2[1]), zz);
    __half2 t2 = __hmax2(__hadd2(sh2[2], dh2[2]), zz);
    __half2 t3 = __hmax2(__hadd2(sh2[3], dh2[3]), zz);
    uint4 v;
    v.x = *reinterpret_cast<uint32_t*>(&t0);
    v.y = *reinterpret_cast<uint32_t*>(&t1);
    v.z = *reinterpret_cast<uint32_t*>(&t2);
    v.w = *reinterpret_cast<uint32_t*>(&t3);
    return v;
}

// ============================================================================
// prep_kernel bodies
// ============================================================================

// HMMA projection for f_src / f_dst, 2 batches per CTA (w converted once).
// C[n][d] = x^T[n][c] @ w[d][c], +bias -> fp16.
// smem: A [4kd][64n][128B] @0, B [4kd][128d][128B] @32768.
__device__ void proj_mma2(char* smc, int mat, int b0,
                          const float* __restrict__ x,
                          const float* __restrict__ w,
                          const float* __restrict__ bias)
{
    __shared__ float s_bias[128];
    const uint32_t sb = smem_u32(smc);
    const int tid = threadIdx.x, wid = tid >> 5, lane = tid & 31;

    // B tiles: w fp16 swizzled (converted once, reused for both b)
#pragma unroll
    for (int t = 0; t < 64; t++) {
        int i = tid + 256 * t;                 // 0..16383 float2 pairs
        int d = i >> 7, c2 = i & 127;
        float2 v = *reinterpret_cast<const float2*>(&w[d * 256 + c2 * 2]);
        int c = c2 * 2, kd = c >> 6, cl = c & 63;
        uint32_t addr = (uint32_t)(32768 + kd * 16384 + d * 128 +
                        ((((cl >> 3) ^ (d & 7)) << 4) | ((cl * 2) & 15)));
        *reinterpret_cast<uint32_t*>(smc + addr) = packh2(v.x, v.y);
    }
    if (tid < 128) s_bias[tid] = bias[tid];

    const int im = wid & 3, ih = wid >> 2;
    const int rowinm = lane & 7, mi = lane >> 3;
    const int a_kx = mi >> 1, a_rl = ((mi & 1) << 3) + rowinm;
    const int b_rl = ((mi >> 1) << 3) + rowinm, b_sw = rowinm, b_kx = mi & 1;
    const int a_r = im * 16 + a_rl;
    const int ccol = (lane & 3) * 2;
    const int n0 = im * 16 + (lane >> 2);

#pragma unroll 1
    for (int lb = 0; lb < 2; lb++) {
        const int b = b0 + lb;
        // A tiles: x^T fp16 swizzled
        {
            const float* xb = x + (size_t)b * CC * NN;
#pragma unroll
            for (int t = 0; t < 16; t++) {
                int i = tid + 256 * t;             // 0..4095 float4 over n
                int c = i >> 4, nn0 = (i & 15) * 4;
                float4 v = *reinterpret_cast<const float4*>(&xb[c * 64 + nn0]);
                int kd = c >> 6, cl = c & 63;
                float vv[4] = {v.x, v.y, v.z, v.w};
#pragma unroll
                for (int j = 0; j < 4; j++) {
                    int n = nn0 + j;
                    uint32_t addr = (uint32_t)(kd * 8192 + n * 128 +
                                    ((((cl >> 3) ^ (n & 7)) << 4) | ((cl * 2) & 15)));
                    *reinterpret_cast<__half*>(smc + addr) = __float2half_rn(vv[j]);
                }
            }
        }
        __syncthreads();

        float c[8][4];
#pragma unroll
        for (int i = 0; i < 8; i++)
#pragma unroll
            for (int j = 0; j < 4; j++) c[i][j] = 0.f;

#pragma unroll
        for (int ks = 0; ks < 16; ks++) {
            int kd = ks >> 2, ksl = ks & 3;
            uint32_t aH[4];
            ldmx4(aH, sb + (uint32_t)(kd * 8192 + a_r * 128 +
                                      (((ksl * 2 + a_kx) ^ (a_r & 7)) << 4)));
            uint32_t kco = (uint32_t)(((ksl * 2 + b_kx) ^ b_sw) << 4);
#pragma unroll
            for (int q = 0; q < 4; q++) {
                uint32_t bh[4];
                ldmx4(bh, sb + (uint32_t)(32768 + kd * 16384 +
                                          (ih * 64 + q * 16 + b_rl) * 128) + kco);
                mma16816(c[2 * q],     aH, bh[0], bh[1]);
                mma16816(c[2 * q + 1], aH, bh[2], bh[3]);
            }
        }

        __half* tgt = &g_ft[mat][b][0][0];
#pragma unroll
        for (int nt = 0; nt < 8; nt++) {
            int d = ih * 64 + nt * 8 + ccol;
            float bv0 = s_bias[d], bv1 = s_bias[d + 1];
            *reinterpret_cast<uint32_t*>(&tgt[n0 * DD + d]) =
                packh2(c[nt][0] + bv0, c[nt][1] + bv1);
            *reinterpret_cast<uint32_t*>(&tgt[(n0 + 8) * DD + d]) =
                packh2(c[nt][2] + bv0, c[nt][3] + bv1);
        }
        __syncthreads();   // protect A region before next lb's fill
    }
}

// exact fp32 projection for f_arr, d-quarter per CTA (bit-identical order).
__device__ void proj_f32q(float* sh, int b, int dq,
                          const float* __restrict__ x,
                          const float* __restrict__ w,
                          const float* __restrict__ bias)
{
    float (*Ws)[36] = reinterpret_cast<float(*)[36]>(sh);            // 32x36
    float (*Xs)[68] = reinterpret_cast<float(*)[68]>(sh + 1152);     // 32x68
    const int tid = threadIdx.x;
    const int tx  = tid & 15;
    const int ty  = tid >> 4;
    const int d0  = dq * 32;

    float acc[2][4];
#pragma unroll
    for (int i = 0; i < 2; i++)
#pragma unroll
        for (int j = 0; j < 4; j++) acc[i][j] = 0.f;

    const float* xb = x + (size_t)b * CC * NN;

#pragma unroll 1
    for (int c0 = 0; c0 < CC; c0 += 32) {
#pragma unroll
        for (int j = 0; j < 4; j++) {
            int i = tid + 256 * j;                 // 0..1023
            int dd = i >> 5, kk = i & 31;
            Ws[kk][dd] = w[(d0 + dd) * CC + c0 + kk];
        }
#pragma unroll
        for (int j = 0; j < 8; j++) {
            int i = tid + 256 * j;
            int kk = i >> 6, n = i & 63;
            Xs[kk][n] = xb[(c0 + kk) * NN + n];
        }
        __syncthreads();
#pragma unroll
        for (int kk = 0; kk < 32; kk++) {
            float a[2], xv[4];
            a[0] = Ws[kk][ty * 2];
            a[1] = Ws[kk][ty * 2 + 1];
#pragma unroll
            for (int j = 0; j < 4; j++) xv[j] = Xs[kk][tx * 4 + j];
#pragma unroll
            for (int i = 0; i < 2; i++)
#pragma unroll
                for (int j = 0; j < 4; j++) acc[i][j] += a[i] * xv[j];
        }
        __syncthreads();
    }

    float* out = &g_farr[b][0][0];
#pragma unroll
    for (int i = 0; i < 2; i++) {
        int d = d0 + ty * 2 + i;
        float bv = bias[d];
        float4 v = make_float4(acc[i][0] + bv, acc[i][1] + bv,
                               acc[i][2] + bv, acc[i][3] + bv);
        *reinterpret_cast<float4*>(&out[d * NN + tx * 4]) = v;
    }
}

__global__ void __launch_bounds__(256) prep_kernel(
    const float* __restrict__ x,
    const float* __restrict__ w_src, const float* __restrict__ b_src,
    const float* __restrict__ w_dst, const float* __restrict__ b_dst,
    const float* __restrict__ w_arr, const float* __restrict__ b_arr,
    const float* __restrict__ w1, const float* __restrict__ w2,
    const float* __restrict__ w3)
{
    extern __shared__ char smc[];
    const int bid = blockIdx.x, tid = threadIdx.x;
    if (bid < 64) {
        int mat = bid >> 5, bp = bid & 31;
        proj_mma2(smc, mat, bp * 2, x, mat ? w_dst : w_src, mat ? b_dst : b_src);
    } else if (bid < 320) {
        int r = bid - 64;
        proj_f32q(reinterpret_cast<float*>(smc), r >> 2, r & 3, x, w_arr, b_arr);
    } else if (bid < 448) {
        int idx = (bid - 320) * 256 + tid;                // 32768 elems
        g_w2h[idx] = __float2half_rn(w2[idx]);
    } else if (bid < 576) {
        int base = (bid - 448) * 512 + tid;               // 65536 elems
        __half* w1h = &g_w1h[0][0];
        w1h[base]       = __float2half_rn(w1[base]);
        w1h[base + 256] = __float2half_rn(w1[base + 256]);
    } else {
        int idx = (bid - 576) * 256 + tid;                // 16384 elems
        int o = idx >> 7, p = idx & 127;
        g_w3t[o * 128 + p] = __float2half_rn(w3[p * 128 + o]);
    }
}

// ============================================================================
// Stage-2: sp HMMA (0..127) | move HMMA (128..191) | g HMMA (192..255)
// ============================================================================

__device__ void sp_mma(char* smc, int type, int b, const float* __restrict__ b1)
{
    __shared__ float s_b1[256];
    const uint32_t sb = smem_u32(smc);
    const int tid = threadIdx.x, wid = tid >> 5, lane = tid & 31;

#pragma unroll
    for (int t = 0; t < 4; t++) {
        int i = tid + 256 * t;                     // 0..1023
        int n = i >> 4, g = i & 15, kd = g >> 3, cg = g & 7;
        uint4 v = *reinterpret_cast<const uint4*>(&g_ft[type][b][n][g * 8]);
        *reinterpret_cast<uint4*>(smc + kd * 8192 + n * 128 +
                                  ((cg ^ (n & 7)) << 4)) = v;
    }
#pragma unroll
    for (int t = 0; t < 16; t++) {
        int i = tid + 256 * t;                     // 0..4095
        int h = i >> 4, g = i & 15, kd = g >> 3, cg = g & 7;
        uint4 v = *reinterpret_cast<const uint4*>(&g_w1h[h][type * 128 + g * 8]);
        *reinterpret_cast<uint4*>(smc + 16384 + kd * 32768 + h * 128 +
                                  ((cg ^ (h & 7)) << 4)) = v;
    }
    s_b1[tid] = (type == 0) ? b1[tid] : 0.f;
    __syncthreads();

    const int im = wid & 3, ih = wid >> 2;
    const int rowinm = lane & 7, mi = lane >> 3;
    const int a_kx = mi >> 1, a_rl = ((mi & 1) << 3) + rowinm;
    const int b_rl = ((mi >> 1) << 3) + rowinm, b_sw = rowinm, b_kx = mi & 1;
    const int a_r = im * 16 + a_rl;

    float c[16][4];
#pragma unroll
    for (int i = 0; i < 16; i++)
#pragma unroll
        for (int j = 0; j < 4; j++) c[i][j] = 0.f;

#pragma unroll
    for (int ks = 0; ks < 8; ks++) {
        int kd = ks >> 2, ksl = ks & 3;
        uint32_t aH[4];
        ldmx4(aH, sb + (uint32_t)(kd * 8192 + a_r * 128 +
                                  (((ksl * 2 + a_kx) ^ (a_r & 7)) << 4)));
        uint32_t kco = (uint32_t)(((ksl * 2 + b_kx) ^ b_sw) << 4);
        uint32_t bbase = sb + (uint32_t)(16384 + kd * 32768);
#pragma unroll
        for (int q = 0; q < 8; q++) {
            uint32_t bh[4];
            ldmx4(bh, bbase + (uint32_t)((ih * 128 + q * 16 + b_rl) * 128) + kco);
            mma16816(c[2 * q],     aH, bh[0], bh[1]);
            mma16816(c[2 * q + 1], aH, bh[2], bh[3]);
        }
    }

    const int ccol = (lane & 3) * 2;
    __half* tgt = type ? &g_dstp_h[b][0][0] : &g_srcp_h[b][0][0];
    const int n0 = im * 16 + (lane >> 2);
#pragma unroll
    for (int nt = 0; nt < 16; nt++) {
        int h = ih * 128 + nt * 8 + ccol;
        float bv0 = s_b1[h], bv1 = s_b1[h + 1];
        *reinterpret_cast<uint32_t*>(&tgt[n0 * HH + h]) =
            packh2(c[nt][0] + bv0, c[nt][1] + bv1);
        *reinterpret_cast<uint32_t*>(&tgt[(n0 + 8) * HH + h]) =
            packh2(c[nt][2] + bv0, c[nt][3] + bv1);
    }
}

__device__ void move_mma(char* smc, int b, float* __restrict__ out_move)
{
    const uint32_t sb = smem_u32(smc);
    const int tid = threadIdx.x, wid = tid >> 5, lane = tid & 31;

#pragma unroll
    for (int t = 0; t < 4; t++) {
        int i = tid + 256 * t;                     // 0..1023
        int n = i >> 4, g = i & 15, kd = g >> 3, cg = g & 7;
        uint32_t off = (uint32_t)(kd * 8192 + n * 128 + ((cg ^ (n & 7)) << 4));
        *reinterpret_cast<uint4*>(smc + off) =
            *reinterpret_cast<const uint4*>(&g_ft[0][b][n][g * 8]);
        *reinterpret_cast<uint4*>(smc + 16384 + off) =
            *reinterpret_cast<const uint4*>(&g_ft[1][b][n][g * 8]);
    }
    __syncthreads();

    const int im = wid & 3, in = wid >> 2;
    const int rowinm = lane & 7, mi = lane >> 3;
    const int a_kx = mi >> 1, a_rl = ((mi & 1) << 3) + rowinm;
    const int b_rl = ((mi >> 1) << 3) + rowinm, b_sw = rowinm, b_kx = mi & 1;
    const int a_r = im * 16 + a_rl;

    float c[4][4];
#pragma unroll
    for (int i = 0; i < 4; i++)
#pragma unroll
        for (int j = 0; j < 4; j++) c[i][j] = 0.f;

#pragma unroll
    for (int ks = 0; ks < 8; ks++) {
        int kd = ks >> 2, ksl = ks & 3;
        uint32_t aH[4];
        ldmx4(aH, sb + (uint32_t)(kd * 8192 + a_r * 128 +
                                  (((ksl * 2 + a_kx) ^ (a_r & 7)) << 4)));
        uint32_t kco = (uint32_t)(((ksl * 2 + b_kx) ^ b_sw) << 4);
#pragma unroll
        for (int q = 0; q < 2; q++) {
            uint32_t bh[4];
            ldmx4(bh, sb + (uint32_t)(16384 + kd * 8192 +
                                      (in * 32 + q * 16 + b_rl) * 128) + kco);
            mma16816(c[2 * q],     aH, bh[0], bh[1]);
            mma16816(c[2 * q + 1], aH, bh[2], bh[3]);
        }
    }

    const int ccol = (lane & 3) * 2;
    const int n0 = im * 16 + (lane >> 2);
#pragma unroll
    for (int nt = 0; nt < 4; nt++) {
        int m = in * 32 + nt * 8 + ccol;
        *reinterpret_cast<float2*>(&out_move[(b * NN + n0) * NN + m]) =
            make_float2(c[nt][0] * SCALE_V, c[nt][1] * SCALE_V);
        *reinterpret_cast<float2*>(&out_move[(b * NN + n0 + 8) * NN + m]) =
            make_float2(c[nt][2] * SCALE_V, c[nt][3] * SCALE_V);
    }
}

__device__ void g_mma(char* smc, int b, const float* __restrict__ b3)
{
    const uint32_t sb = smem_u32(smc);
    const int tid = threadIdx.x, wid = tid >> 5, lane = tid & 31;

#pragma unroll
    for (int t = 0; t < 32; t++) {
        int i = tid + 256 * t;                     // 0..8191
        int p = i >> 6, k = i & 63;
        float v = g_farr[b][p][k];
        int kd = p >> 6, pl = p & 63;
        uint32_t addr = (uint32_t)(kd * 8192 + k * 128 +
                        ((((pl >> 3) ^ (k & 7)) << 4) | ((pl * 2) & 15)));
        *reinterpret_cast<__half*>(smc + addr) = __float2half_rn(v);
    }
#pragma unroll
    for (int t = 0; t < 8; t++) {
        int i = tid + 256 * t;                     // 0..2047 uint4
        int o = i >> 4, g = i & 15, kd = g >> 3, cg = g & 7;
        uint4 v = *reinterpret_cast<const uint4*>(&g_w3t[o * 128 + g * 8]);
        *reinterpret_cast<uint4*>(smc + 16384 + kd * 16384 + o * 128 +
                                  ((cg ^ (o & 7)) << 4)) = v;
    }
    __syncthreads();

    const int im = wid & 3, ih = wid >> 2;
    const int rowinm = lane & 7, mi = lane >> 3;
    const int a_kx = mi >> 1, a_rl = ((mi & 1) << 3) + rowinm;
    const int b_rl = ((mi >> 1) << 3) + rowinm, b_sw = rowinm, b_kx = mi & 1;
    const int a_r = im * 16 + a_rl;

    float c[8][4];
#pragma unroll
    for (int i = 0; i < 8; i++)
#pragma unroll
        for (int j = 0; j < 4; j++) c[i][j] = 0.f;

#pragma unroll
    for (int ks = 0; ks < 8; ks++) {
        int kd = ks >> 2, ksl = ks & 3;
        uint32_t aH[4];
        ldmx4(aH, sb + (uint32_t)(kd * 8192 + a_r * 128 +
                                  (((ksl * 2 + a_kx) ^ (a_r & 7)) << 4)));
        uint32_t kco = (uint32_t)(((ksl * 2 + b_kx) ^ b_sw) << 4);
#pragma unroll
        for (int q = 0; q < 4; q++) {
            uint32_t bh[4];
            ldmx4(bh, sb + (uint32_t)(16384 + kd * 16384 +
                                      (ih * 64 + q * 16 + b_rl) * 128) + kco);
            mma16816(c[2 * q],     aH, bh[0], bh[1]);
            mma16816(c[2 * q + 1], aH, bh[2], bh[3]);
        }
    }

    const int ccol = (lane & 3) * 2;
    const int k0 = im * 16 + (lane >> 2);
#pragma unroll
    for (int nt = 0; nt < 8; nt++) {
        int o = ih * 64 + nt * 8 + ccol;
        *reinterpret_cast<uint32_t*>(&g_Gh[b * 8192 + k0 * 128 + o]) =
            packh2(c[nt][0], c[nt][1]);
        *reinterpret_cast<uint32_t*>(&g_Gh[b * 8192 + (k0 + 8) * 128 + o]) =
            packh2(c[nt][2], c[nt][3]);
    }

    if (tid < 64) {
        float acc = 0.f;
#pragma unroll 4
        for (int p = 0; p < 128; p++)
            acc += b3[p] * g_farr[b][p][tid];
        g_cv[b][tid] = acc;
    }
}

__global__ void __launch_bounds__(256) stage2_kernel(
    const float* __restrict__ b1, const float* __restrict__ b3,
    float* __restrict__ out_move)
{
    extern __shared__ char s2[];
    const int bid = blockIdx.x;
    if (bid < 128)      sp_mma(s2, bid & 1, bid >> 1, b1);
    else if (bid < 192) move_mma(s2, bid - 128, out_move);
    else                g_mma(s2, bid - 192, b3);
}

// ============================================================================
// Main (hot): unchanged (bit-identical path).
// ============================================================================
__global__ void __launch_bounds__(256, 2) main_kernel(
    const float* __restrict__ b2, float* __restrict__ out_arrow)
{
    extern __shared__ char smc[];
    __shared__ float  s_cv[64];
    __shared__ float  s_b2[128];
    __shared__ __half s_dst[2][256];

    const uint32_t sb = smem_u32(smc);
    const int tid  = threadIdx.x;
    const int wid  = tid >> 5;
    const int lane = tid & 31;
    const int mt = blockIdx.x, b = blockIdx.y, m0 = mt * 2;

    const int ABUF = 65536;
    const int im = wid & 3;
    const int in = wid >> 2;

    const int rowinm = lane & 7, mi = lane >> 3;
    const int a_kx = mi >> 1;
    const int a_rl = ((mi & 1) << 3) + rowinm;
    const int b_rl = ((mi >> 1) << 3) + rowinm;
    const int b_sw = rowinm;
    const int b_kx = mi & 1;

    const int ag_grp  = tid & 7;
    const int ag_row0 = tid >> 3;

    {
        for (int i = tid; i < 4096; i += 256) {
            int o = i >> 5, grp = i & 31;
            int kc = grp >> 3, cgl = grp & 7;
            const uint4* src = reinterpret_cast<const uint4*>(g_w2h + o * 256 + grp * 8);
            uint32_t dst = (uint32_t)(kc * 16384 + o * 128 + ((cgl ^ (o & 7)) << 4));
            *reinterpret_cast<uint4*>(smc + dst) = *src;
        }
        if (tid < 64)  s_cv[tid] = g_cv[b][tid];
        if (tid < 128) s_b2[tid] = b2[tid];
        if (tid < 64) {
            int lm = tid >> 5, grp = tid & 31;
            *reinterpret_cast<uint4*>(&s_dst[lm][grp * 8]) =
                *reinterpret_cast<const uint4*>(&g_dstp_h[b][m0 + lm][grp * 8]);
        }
#pragma unroll
        for (int j = 0; j < 4; j++) {
            int row = ag_row0 + 32 * j;
            int n = row & 63, lm = row >> 6;
            uint4 s = *reinterpret_cast<const uint4*>(&g_srcp_h[b][n][ag_grp * 8]);
            uint4 d = *reinterpret_cast<const uint4*>(&g_dstp_h[b][m0 + lm][ag_grp * 8]);
            uint4 v = reluadd4(s, d);
            uint32_t off = (uint32_t)(row * 128 + ((ag_grp ^ (row & 7)) << 4));
            *reinterpret_cast<uint4*>(smc + ABUF + off) = v;
        }
    }
    __syncthreads();

    float c1[2][8][4];
#pragma unroll
    for (int m = 0; m < 2; m++)
#pragma unroll
        for (int i = 0; i < 8; i++)
#pragma unroll
            for (int j = 0; j < 4; j++) c1[m][i][j] = 0.f;

#pragma unroll 1
    for (int kc = 0; kc < 4; kc++) {
        const uint32_t curA = sb + (uint32_t)(ABUF + ((kc & 1) << 14));
        const uint32_t wHi  = sb + (uint32_t)(kc * 16384);

        uint4 ps[4];
        if (kc < 3) {
#pragma unroll
            for (int j = 0; j < 4; j++) {
                int row = ag_row0 + 32 * j;
                int n = row & 63;
                ps[j] = *reinterpret_cast<const uint4*>(
                    &g_srcp_h[b][n][(kc + 1) * 64 + ag_grp * 8]);
            }
        } else {
#pragma unroll
            for (int t = 0; t < 4; t++) {
                int i = tid + 256 * t;
                ps[t] = *reinterpret_cast<const uint4*>(
                    &g_Gh[b * 8192 + (i >> 4) * 128 + (i & 15) * 8]);
            }
        }

#pragma unroll
        for (int ks = 0; ks < 2; ks++) {
            uint32_t aH[2][4];
#pragma unroll
            for (int m = 0; m < 2; m++) {
                int a_r = im * 32 + m * 16 + a_rl;
                uint32_t co = (uint32_t)(((ks * 2 + a_kx) ^ (a_r & 7)) << 4);
                ldmx4(aH[m], curA + (uint32_t)(a_r * 128) + co);
            }
            uint32_t kco = (uint32_t)(((ks * 2 + b_kx) ^ b_sw) << 4);
            uint32_t bh[4][4];
#pragma unroll
            for (int q = 0; q < 4; q++) {
                int o_row = in * 64 + q * 16 + b_rl;
                ldmx4(bh[q], wHi + (uint32_t)(o_row * 128) + kco);
            }
#pragma unroll
            for (int q = 0; q < 4; q++)
#pragma unroll
                for (int m = 0; m < 2; m++) {
                    mma16816(c1[m][2 * q],     aH[m], bh[q][0], bh[q][1]);
                    mma16816(c1[m][2 * q + 1], aH[m], bh[q][2], bh[q][3]);
                }
        }

        uint4 pv[4];
        if (kc < 3) {
#pragma unroll
            for (int j = 0; j < 4; j++) {
                int row = ag_row0 + 32 * j;
                int lm = row >> 6;
                uint4 d = *reinterpret_cast<const uint4*>(
                    &s_dst[lm][(kc + 1) * 64 + ag_grp * 8]);
                pv[j] = reluadd4(ps[j], d);
            }
        } else {
#pragma unroll
            for (int t = 0; t < 4; t++) pv[t] = ps[t];
        }

#pragma unroll
        for (int ks = 2; ks < 4; ks++) {
            uint32_t aH[2][4];
#pragma unroll
            for (int m = 0; m < 2; m++) {
                int a_r = im * 32 + m * 16 + a_rl;
                uint32_t co = (uint32_t)(((ks * 2 + a_kx) ^ (a_r & 7)) << 4);
                ldmx4(aH[m], curA + (uint32_t)(a_r * 128) + co);
            }
            uint32_t kco = (uint32_t)(((ks * 2 + b_kx) ^ b_sw) << 4);
            uint32_t bh[4][4];
#pragma unroll
            for (int q = 0; q < 4; q++) {
                int o_row = in * 64 + q * 16 + b_rl;
                ldmx4(bh[q], wHi + (uint32_t)(o_row * 128) + kco);
            }
#pragma unroll
            for (int q = 0; q < 4; q++)
#pragma unroll
                for (int m = 0; m < 2; m++) {
                    mma16816(c1[m][2 * q],     aH[m], bh[q][0], bh[q][1]);
                    mma16816(c1[m][2 * q + 1], aH[m], bh[q][2], bh[q][3]);
                }
        }

        if (kc < 3) {
            char* obuf = smc + ABUF + (((kc + 1) & 1) << 14);
#pragma unroll
            for (int j = 0; j < 4; j++) {
                int row = ag_row0 + 32 * j;
                uint32_t off = (uint32_t)(row * 128 + ((ag_grp ^ (row & 7)) << 4));
                *reinterpret_cast<uint4*>(obuf + off) = pv[j];
            }
        } else {
#pragma unroll
            for (int t = 0; t < 4; t++) {
                int i = tid + 256 * t;
                int r = i >> 4, grp = i & 15;
                int kh = grp >> 3, cgl = grp & 7;
                uint32_t dst = (uint32_t)(ABUF + kh * 8192 + r * 128 +
                                          ((cgl ^ (r & 7)) << 4));
                *reinterpret_cast<uint4*>(smc + dst) = pv[t];
            }
        }
        __syncthreads();
    }

    const int ccol = (lane & 3) * 2;
    uint32_t aH2[2][4][4];
#pragma unroll
    for (int m = 0; m < 2; m++)
#pragma unroll
        for (int ko = 0; ko < 4; ko++) {
#pragma unroll
            for (int hn = 0; hn < 2; hn++) {
                int nt = 2 * ko + hn;
                float bv0 = s_b2[in * 64 + nt * 8 + ccol];
                float bv1 = s_b2[in * 64 + nt * 8 + ccol + 1];
                aH2[m][ko][hn * 2]     = packh2(fmaxf(c1[m][nt][0] + bv0, 0.f),
                                                fmaxf(c1[m][nt][1] + bv1, 0.f));
                aH2[m][ko][hn * 2 + 1] = packh2(fmaxf(c1[m][nt][2] + bv0, 0.f),
                                                fmaxf(c1[m][nt][3] + bv1, 0.f));
            }
        }

    float c2[2][8][4];
#pragma unroll
    for (int m = 0; m < 2; m++)
#pragma unroll
        for (int i = 0; i < 8; i++)
#pragma unroll
            for (int j = 0; j < 4; j++) c2[m][i][j] = 0.f;

    const uint32_t gBase = sb + (uint32_t)(ABUF + in * 8192);
#pragma unroll
    for (int ko = 0; ko < 4; ko++) {
        uint32_t kco = (uint32_t)(((ko * 2 + b_kx) ^ b_sw) << 4);
        uint32_t bh[4][4];
#pragma unroll
        for (int q = 0; q < 4; q++)
            ldmx4(bh[q], gBase + (uint32_t)((q * 16 + b_rl) * 128) + kco);
#pragma unroll
        for (int q = 0; q < 4; q++)
#pragma unroll
            for (int m = 0; m < 2; m++) {
                mma16816(c2[m][2 * q],     aH2[m][ko], bh[q][0], bh[q][1]);
                mma16816(c2[m][2 * q + 1], aH2[m][ko], bh[q][2], bh[q][3]);
            }
    }

    float* rbuf = reinterpret_cast<float*>(smc);
    if (in == 1) {
#pragma unroll
        for (int m = 0; m < 2; m++) {
            int r0 = im * 32 + m * 16 + (lane >> 2);
#pragma unroll
            for (int kt = 0; kt < 8; kt++) {
                int k = kt * 8 + ccol;
                *reinterpret_cast<float2*>(&rbuf[r0 * 72 + k]) =
                    make_float2(c2[m][kt][0], c2[m][kt][1]);
                *reinterpret_cast<float2*>(&rbuf[(r0 + 8) * 72 + k]) =
                    make_float2(c2[m][kt][2], c2[m][kt][3]);
            }
        }
    }
    __syncthreads();
    if (in == 0) {
#pragma unroll
        for (int m = 0; m < 2; m++) {
            int r0 = im * 32 + m * 16 + (lane >> 2);
            int r1 = r0 + 8;
            float* p0 = out_arrow + (((size_t)b * 4096 +
                                      (size_t)(r0 & 63) * 64 + m0 + (r0 >> 6)) << 6);
            float* p1 = out_arrow + (((size_t)b * 4096 +
                                      (size_t)(r1 & 63) * 64 + m0 + (r1 >> 6)) << 6);
#pragma unroll
            for (int kt = 0; kt < 8; kt++) {
                int k = kt * 8 + ccol;
                float2 q0 = *reinterpret_cast<const float2*>(&rbuf[r0 * 72 + k]);
                float2 q1 = *reinterpret_cast<const float2*>(&rbuf[r1 * 72 + k]);
                float cv0 = s_cv[k], cv1 = s_cv[k + 1];
                float2 v0 = make_float2((c2[m][kt][0] + q0.x + cv0) * SCALE_V,
                                        (c2[m][kt][1] + q0.y + cv1) * SCALE_V);
                float2 v1 = make_float2((c2[m][kt][2] + q1.x + cv0) * SCALE_V,
                                        (c2[m][kt][3] + q1.y + cv1) * SCALE_V);
                *reinterpret_cast<float2*>(p0 + k) = v0;
                *reinterpret_cast<float2*>(p1 + k) = v1;
            }
        }
    }
}

// ============================================================================
// launch
// ============================================================================
extern "C" void kernel_launch(void* const* d_in, const int* in_sizes, int n_in,
                              void* d_out, int out_size)
{
    (void)in_sizes; (void)n_in; (void)out_size;
    const float* x     = (const float*)d_in[0];
    const float* w_src = (const float*)d_in[1];
    const float* b_src = (const float*)d_in[2];
    const float* w_dst = (const float*)d_in[3];
    const float* b_dst = (const float*)d_in[4];
    const float* w_arr = (const float*)d_in[5];
    const float* b_arr = (const float*)d_in[6];
    const float* w1    = (const float*)d_in[7];
    const float* b1    = (const float*)d_in[8];
    const float* w2    = (const float*)d_in[9];
    const float* b2    = (const float*)d_in[10];
    const float* w3    = (const float*)d_in[11];
    const float* b3    = (const float*)d_in[12];

    float* out_move  = (float*)d_out;                       // 64*64*64
    float* out_arrow = (float*)d_out + 64 * 64 * 64;        // 64*4096*64

    constexpr int SMEM_MAIN = 98304;
    constexpr int SMEM_S2   = 81920;
    cudaFuncSetAttribute(main_kernel, cudaFuncAttributeMaxDynamicSharedMemorySize,
                         SMEM_MAIN);
    cudaFuncSetAttribute(stage2_kernel, cudaFuncAttributeMaxDynamicSharedMemorySize,
                         SMEM_S2);
    cudaFuncSetAttribute(prep_kernel, cudaFuncAttributeMaxDynamicSharedMemorySize,
                         SMEM_MAIN);

    prep_kernel<<<640, 256, SMEM_MAIN>>>(x, w_src, b_src, w_dst, b_dst,
                                         w_arr, b_arr, w1, w2, w3);
    stage2_kernel<<<256, 256, SMEM_S2>>>(b1, b3, out_move);
    main_kernel<<<dim3(32, 64), 256, SMEM_MAIN>>>(b2, out_arrow);
}

// round 15
// speedup vs baseline: 1.1450x; 1.1450x over previous
#include <cuda_runtime.h>
#include <cuda_fp16.h>
#include <cstdint>

// ---------------- problem constants ----------------
#define BB 64
#define CC 256
#define DD 128
#define NN 64
#define HH 256
#define SCALE_V 0.08838834764831845f   // 1/sqrt(128)

// ---------------- device scratch ----------------
__device__ float g_cv[BB][NN];           // c[b][k]
// fp16 images
__device__ __align__(16) __half g_ft[3][BB][NN][DD];    // f_src/f_dst/f_arr transposed
__device__ __align__(16) __half g_w1h[HH][HH];          // w1 fp16 [h][2d]
__device__ __align__(16) __half g_w3t[DD * DD];         // w3^T fp16 [o][p]
__device__ __align__(16) __half g_srcp_h[BB][NN][HH];   // src_p (+b1), fp16
__device__ __align__(16) __half g_dstp_h[BB][NN][HH];   // dst_p, fp16
__device__ __align__(16) __half g_w2h[32768];           // [o(128)][h(256)]
__device__ __align__(16) __half g_Gh[BB * 8192];        // [b][k_out(64)][o(128)]

// ---------------- helpers ----------------
__device__ __forceinline__ uint32_t smem_u32(const void* p) {
    uint32_t a;
    asm("{ .reg .u64 t; cvta.to.shared.u64 t, %1; cvt.u32.u64 %0, t; }" : "=r"(a) : "l"(p));
    return a;
}
__device__ __forceinline__ void ldmx4(uint32_t r[4], uint32_t addr) {
    asm volatile("ldmatrix.sync.aligned.m8n8.x4.shared.b16 {%0,%1,%2,%3}, [%4];"
                 : "=r"(r[0]), "=r"(r[1]), "=r"(r[2]), "=r"(r[3]) : "r"(addr));
}
__device__ __forceinline__ void mma16816(float c[4], const uint32_t a[4],
                                         uint32_t b0, uint32_t b1) {
    asm volatile(
        "mma.sync.aligned.m16n8k16.row.col.f32.f16.f16.f32 "
        "{%0,%1,%2,%3}, {%4,%5,%6,%7}, {%8,%9}, {%0,%1,%2,%3};"
        : "+f"(c[0]), "+f"(c[1]), "+f"(c[2]), "+f"(c[3])
        : "r"(a[0]), "r"(a[1]), "r"(a[2]), "r"(a[3]), "r"(b0), "r"(b1));
}
__device__ __forceinline__ uint32_t packh2(float x, float y) {
    __half2 h = __floats2half2_rn(x, y);
    return *reinterpret_cast<uint32_t*>(&h);
}
__device__ __forceinline__ uint4 reluadd4(uint4 s, uint4 d) {
    const __half2 zz = __floats2half2_rn(0.f, 0.f);
    const __half2* sh2 = reinterpret_cast<const __half2*>(&s);
    const __half2* dh2 = reinterpret_cast<const __half2*>(&d);
    __half2 t0 = __hmax2(__hadd2(sh2[0], dh2[0]), zz);
    __half2 t1 = __hmax2(__hadd2(sh2[1], dh2[1]), zz);
    __half2 t2 = __hmax2(__hadd2(sh2[2], dh2[2]), zz);
    __half2 t3 = __hmax2(__hadd2(sh2[3], dh2[3]), zz);
    uint4 v;
    v.x = *reinterpret_cast<uint32_t*>(&t0);
    v.y = *reinterpret_cast<uint32_t*>(&t1);
    v.z = *reinterpret_cast<uint32_t*>(&t2);
    v.w = *reinterpret_cast<uint32_t*>(&t3);
    return v;
}

// ============================================================================
// prep_kernel: HMMA projections (all 3 mats) + weight conversions
// ============================================================================

// HMMA projection, 2 batches per CTA (w converted once).
// C[n][d] = x^T[n][c] @ w[d][c], +bias -> fp16 g_ft[mat].
// smem: A [4kd][64n][128B] @0, B [4kd][128d][128B] @32768.
__device__ void proj_mma2(char* smc, int mat, int b0,
                          const float* __restrict__ x,
                          const float* __restrict__ w,
                          const float* __restrict__ bias)
{
    __shared__ float s_bias[128];
    const uint32_t sb = smem_u32(smc);
    const int tid = threadIdx.x, wid = tid >> 5, lane = tid & 31;

    // B tiles: w fp16 swizzled (converted once, reused for both b)
#pragma unroll
    for (int t = 0; t < 64; t++) {
        int i = tid + 256 * t;                 // 0..16383 float2 pairs
        int d = i >> 7, c2 = i & 127;
        float2 v = *reinterpret_cast<const float2*>(&w[d * 256 + c2 * 2]);
        int c = c2 * 2, kd = c >> 6, cl = c & 63;
        uint32_t addr = (uint32_t)(32768 + kd * 16384 + d * 128 +
                        ((((cl >> 3) ^ (d & 7)) << 4) | ((cl * 2) & 15)));
        *reinterpret_cast<uint32_t*>(smc + addr) = packh2(v.x, v.y);
    }
    if (tid < 128) s_bias[tid] = bias[tid];

    const int im = wid & 3, ih = wid >> 2;
    const int rowinm = lane & 7, mi = lane >> 3;
    const int a_kx = mi >> 1, a_rl = ((mi & 1) << 3) + rowinm;
    const int b_rl = ((mi >> 1) << 3) + rowinm, b_sw = rowinm, b_kx = mi & 1;
    const int a_r = im * 16 + a_rl;
    const int ccol = (lane & 3) * 2;
    const int n0 = im * 16 + (lane >> 2);

#pragma unroll 1
    for (int lb = 0; lb < 2; lb++) {
        const int b = b0 + lb;
        // A tiles: x^T fp16 swizzled
        {
            const float* xb = x + (size_t)b * CC * NN;
#pragma unroll
            for (int t = 0; t < 16; t++) {
                int i = tid + 256 * t;             // 0..4095 float4 over n
                int c = i >> 4, nn0 = (i & 15) * 4;
                float4 v = *reinterpret_cast<const float4*>(&xb[c * 64 + nn0]);
                int kd = c >> 6, cl = c & 63;
                float vv[4] = {v.x, v.y, v.z, v.w};
#pragma unroll
                for (int j = 0; j < 4; j++) {
                    int n = nn0 + j;
                    uint32_t addr = (uint32_t)(kd * 8192 + n * 128 +
                                    ((((cl >> 3) ^ (n & 7)) << 4) | ((cl * 2) & 15)));
                    *reinterpret_cast<__half*>(smc + addr) = __float2half_rn(vv[j]);
                }
            }
        }
        __syncthreads();

        float c[8][4];
#pragma unroll
        for (int i = 0; i < 8; i++)
#pragma unroll
            for (int j = 0; j < 4; j++) c[i][j] = 0.f;

#pragma unroll
        for (int ks = 0; ks < 16; ks++) {
            int kd = ks >> 2, ksl = ks & 3;
            uint32_t aH[4];
            ldmx4(aH, sb + (uint32_t)(kd * 8192 + a_r * 128 +
                                      (((ksl * 2 + a_kx) ^ (a_r & 7)) << 4)));
            uint32_t kco = (uint32_t)(((ksl * 2 + b_kx) ^ b_sw) << 4);
#pragma unroll
            for (int q = 0; q < 4; q++) {
                uint32_t bh[4];
                ldmx4(bh, sb + (uint32_t)(32768 + kd * 16384 +
                                          (ih * 64 + q * 16 + b_rl) * 128) + kco);
                mma16816(c[2 * q],     aH, bh[0], bh[1]);
                mma16816(c[2 * q + 1], aH, bh[2], bh[3]);
            }
        }

        __half* tgt = &g_ft[mat][b][0][0];
#pragma unroll
        for (int nt = 0; nt < 8; nt++) {
            int d = ih * 64 + nt * 8 + ccol;
            float bv0 = s_bias[d], bv1 = s_bias[d + 1];
            *reinterpret_cast<uint32_t*>(&tgt[n0 * DD + d]) =
                packh2(c[nt][0] + bv0, c[nt][1] + bv1);
            *reinterpret_cast<uint32_t*>(&tgt[(n0 + 8) * DD + d]) =
                packh2(c[nt][2] + bv0, c[nt][3] + bv1);
        }
        __syncthreads();   // protect A region before next lb's fill
    }
}

__global__ void __launch_bounds__(256) prep_kernel(
    const float* __restrict__ x,
    const float* __restrict__ w_src, const float* __restrict__ b_src,
    const float* __restrict__ w_dst, const float* __restrict__ b_dst,
    const float* __restrict__ w_arr, const float* __restrict__ b_arr,
    const float* __restrict__ w1, const float* __restrict__ w2,
    const float* __restrict__ w3)
{
    extern __shared__ char smc[];
    const int bid = blockIdx.x, tid = threadIdx.x;
    if (bid < 96) {
        int mat = bid >> 5, bp = bid & 31;
        const float* w    = (mat == 0) ? w_src : (mat == 1) ? w_dst : w_arr;
        const float* bias = (mat == 0) ? b_src : (mat == 1) ? b_dst : b_arr;
        proj_mma2(smc, mat, bp * 2, x, w, bias);
    } else if (bid < 224) {
        int idx = (bid - 96) * 256 + tid;                 // 32768 elems
        g_w2h[idx] = __float2half_rn(w2[idx]);
    } else if (bid < 352) {
        int base = (bid - 224) * 512 + tid;               // 65536 elems
        __half* w1h = &g_w1h[0][0];
        w1h[base]       = __float2half_rn(w1[base]);
        w1h[base + 256] = __float2half_rn(w1[base + 256]);
    } else {
        int idx = (bid - 352) * 256 + tid;                // 16384 elems
        int o = idx >> 7, p = idx & 127;
        g_w3t[o * 128 + p] = __float2half_rn(w3[p * 128 + o]);
    }
}

// ============================================================================
// Stage-2: sp HMMA (0..127) | move HMMA (128..191) | g HMMA (192..255)
// ============================================================================

__device__ void sp_mma(char* smc, int type, int b, const float* __restrict__ b1)
{
    __shared__ float s_b1[256];
    const uint32_t sb = smem_u32(smc);
    const int tid = threadIdx.x, wid = tid >> 5, lane = tid & 31;

#pragma unroll
    for (int t = 0; t < 4; t++) {
        int i = tid + 256 * t;                     // 0..1023
        int n = i >> 4, g = i & 15, kd = g >> 3, cg = g & 7;
        uint4 v = *reinterpret_cast<const uint4*>(&g_ft[type][b][n][g * 8]);
        *reinterpret_cast<uint4*>(smc + kd * 8192 + n * 128 +
                                  ((cg ^ (n & 7)) << 4)) = v;
    }
#pragma unroll
    for (int t = 0; t < 16; t++) {
        int i = tid + 256 * t;                     // 0..4095
        int h = i >> 4, g = i & 15, kd = g >> 3, cg = g & 7;
        uint4 v = *reinterpret_cast<const uint4*>(&g_w1h[h][type * 128 + g * 8]);
        *reinterpret_cast<uint4*>(smc + 16384 + kd * 32768 + h * 128 +
                                  ((cg ^ (h & 7)) << 4)) = v;
    }
    s_b1[tid] = (type == 0) ? b1[tid] : 0.f;
    __syncthreads();

    const int im = wid & 3, ih = wid >> 2;
    const int rowinm = lane & 7, mi = lane >> 3;
    const int a_kx = mi >> 1, a_rl = ((mi & 1) << 3) + rowinm;
    const int b_rl = ((mi >> 1) << 3) + rowinm, b_sw = rowinm, b_kx = mi & 1;
    const int a_r = im * 16 + a_rl;

    float c[16][4];
#pragma unroll
    for (int i = 0; i < 16; i++)
#pragma unroll
        for (int j = 0; j < 4; j++) c[i][j] = 0.f;

#pragma unroll
    for (int ks = 0; ks < 8; ks++) {
        int kd = ks >> 2, ksl = ks & 3;
        uint32_t aH[4];
        ldmx4(aH, sb + (uint32_t)(kd * 8192 + a_r * 128 +
                                  (((ksl * 2 + a_kx) ^ (a_r & 7)) << 4)));
        uint32_t kco = (uint32_t)(((ksl * 2 + b_kx) ^ b_sw) << 4);
        uint32_t bbase = sb + (uint32_t)(16384 + kd * 32768);
#pragma unroll
        for (int q = 0; q < 8; q++) {
            uint32_t bh[4];
            ldmx4(bh, bbase + (uint32_t)((ih * 128 + q * 16 + b_rl) * 128) + kco);
            mma16816(c[2 * q],     aH, bh[0], bh[1]);
            mma16816(c[2 * q + 1], aH, bh[2], bh[3]);
        }
    }

    const int ccol = (lane & 3) * 2;
    __half* tgt = type ? &g_dstp_h[b][0][0] : &g_srcp_h[b][0][0];
    const int n0 = im * 16 + (lane >> 2);
#pragma unroll
    for (int nt = 0; nt < 16; nt++) {
        int h = ih * 128 + nt * 8 + ccol;
        float bv0 = s_b1[h], bv1 = s_b1[h + 1];
        *reinterpret_cast<uint32_t*>(&tgt[n0 * HH + h]) =
            packh2(c[nt][0] + bv0, c[nt][1] + bv1);
        *reinterpret_cast<uint32_t*>(&tgt[(n0 + 8) * HH + h]) =
            packh2(c[nt][2] + bv0, c[nt][3] + bv1);
    }
}

__device__ void move_mma(char* smc, int b, float* __restrict__ out_move)
{
    const uint32_t sb = smem_u32(smc);
    const int tid = threadIdx.x, wid = tid >> 5, lane = tid & 31;

#pragma unroll
    for (int t = 0; t < 4; t++) {
        int i = tid + 256 * t;                     // 0..1023
        int n = i >> 4, g = i & 15, kd = g >> 3, cg = g & 7;
        uint32_t off = (uint32_t)(kd * 8192 + n * 128 + ((cg ^ (n & 7)) << 4));
        *reinterpret_cast<uint4*>(smc + off) =
            *reinterpret_cast<const uint4*>(&g_ft[0][b][n][g * 8]);
        *reinterpret_cast<uint4*>(smc + 16384 + off) =
            *reinterpret_cast<const uint4*>(&g_ft[1][b][n][g * 8]);
    }
    __syncthreads();

    const int im = wid & 3, in = wid >> 2;
    const int rowinm = lane & 7, mi = lane >> 3;
    const int a_kx = mi >> 1, a_rl = ((mi & 1) << 3) + rowinm;
    const int b_rl = ((mi >> 1) << 3) + rowinm, b_sw = rowinm, b_kx = mi & 1;
    const int a_r = im * 16 + a_rl;

    float c[4][4];
#pragma unroll
    for (int i = 0; i < 4; i++)
#pragma unroll
        for (int j = 0; j < 4; j++) c[i][j] = 0.f;

#pragma unroll
    for (int ks = 0; ks < 8; ks++) {
        int kd = ks >> 2, ksl = ks & 3;
        uint32_t aH[4];
        ldmx4(aH, sb + (uint32_t)(kd * 8192 + a_r * 128 +
                                  (((ksl * 2 + a_kx) ^ (a_r & 7)) << 4)));
        uint32_t kco = (uint32_t)(((ksl * 2 + b_kx) ^ b_sw) << 4);
#pragma unroll
        for (int q = 0; q < 2; q++) {
            uint32_t bh[4];
            ldmx4(bh, sb + (uint32_t)(16384 + kd * 8192 +
                                      (in * 32 + q * 16 + b_rl) * 128) + kco);
            mma16816(c[2 * q],     aH, bh[0], bh[1]);
            mma16816(c[2 * q + 1], aH, bh[2], bh[3]);
        }
    }

    const int ccol = (lane & 3) * 2;
    const int n0 = im * 16 + (lane >> 2);
#pragma unroll
    for (int nt = 0; nt < 4; nt++) {
        int m = in * 32 + nt * 8 + ccol;
        *reinterpret_cast<float2*>(&out_move[(b * NN + n0) * NN + m]) =
            make_float2(c[nt][0] * SCALE_V, c[nt][1] * SCALE_V);
        *reinterpret_cast<float2*>(&out_move[(b * NN + n0 + 8) * NN + m]) =
            make_float2(c[nt][2] * SCALE_V, c[nt][3] * SCALE_V);
    }
}

// g: G^T[k][o] = f_arr^T[k][p] @ w3t[o][p]  (HMMA, A from fp16 g_ft[2]);
//    cv[b][k] = sum_p b3[p] * f16(f_arr)[k][p]  (fp32 accumulate).
__device__ void g_mma(char* smc, int b, const float* __restrict__ b3)
{
    const uint32_t sb = smem_u32(smc);
    const int tid = threadIdx.x, wid = tid >> 5, lane = tid & 31;

    // A: direct fp16 copy of g_ft[2] (layout [k][p]), swizzled
#pragma unroll
    for (int t = 0; t < 4; t++) {
        int i = tid + 256 * t;                     // 0..1023
        int k = i >> 4, g = i & 15, kd = g >> 3, cg = g & 7;
        uint4 v = *reinterpret_cast<const uint4*>(&g_ft[2][b][k][g * 8]);
        *reinterpret_cast<uint4*>(smc + kd * 8192 + k * 128 +
                                  ((cg ^ (k & 7)) << 4)) = v;
    }
    // B: w3t
#pragma unroll
    for (int t = 0; t < 8; t++) {
        int i = tid + 256 * t;                     // 0..2047 uint4
        int o = i >> 4, g = i & 15, kd = g >> 3, cg = g & 7;
        uint4 v = *reinterpret_cast<const uint4*>(&g_w3t[o * 128 + g * 8]);
        *reinterpret_cast<uint4*>(smc + 16384 + kd * 16384 + o * 128 +
                                  ((cg ^ (o & 7)) << 4)) = v;
    }
    __syncthreads();

    const int im = wid & 3, ih = wid >> 2;
    const int rowinm = lane & 7, mi = lane >> 3;
    const int a_kx = mi >> 1, a_rl = ((mi & 1) << 3) + rowinm;
    const int b_rl = ((mi >> 1) << 3) + rowinm, b_sw = rowinm, b_kx = mi & 1;
    const int a_r = im * 16 + a_rl;

    float c[8][4];
#pragma unroll
    for (int i = 0; i < 8; i++)
#pragma unroll
        for (int j = 0; j < 4; j++) c[i][j] = 0.f;

#pragma unroll
    for (int ks = 0; ks < 8; ks++) {
        int kd = ks >> 2, ksl = ks & 3;
        uint32_t aH[4];
        ldmx4(aH, sb + (uint32_t)(kd * 8192 + a_r * 128 +
                                  (((ksl * 2 + a_kx) ^ (a_r & 7)) << 4)));
        uint32_t kco = (uint32_t)(((ksl * 2 + b_kx) ^ b_sw) << 4);
#pragma unroll
        for (int q = 0; q < 4; q++) {
            uint32_t bh[4];
            ldmx4(bh, sb + (uint32_t)(16384 + kd * 16384 +
                                      (ih * 64 + q * 16 + b_rl) * 128) + kco);
            mma16816(c[2 * q],     aH, bh[0], bh[1]);
            mma16816(c[2 * q + 1], aH, bh[2], bh[3]);
        }
    }

    const int ccol = (lane & 3) * 2;
    const int k0 = im * 16 + (lane >> 2);
#pragma unroll
    for (int nt = 0; nt < 8; nt++) {
        int o = ih * 64 + nt * 8 + ccol;
        *reinterpret_cast<uint32_t*>(&g_Gh[b * 8192 + k0 * 128 + o]) =
            packh2(c[nt][0], c[nt][1]);
        *reinterpret_cast<uint32_t*>(&g_Gh[b * 8192 + (k0 + 8) * 128 + o]) =
            packh2(c[nt][2], c[nt][3]);
    }

    // cv from fp16 f_arr row (contiguous), fp32 accumulate
    if (tid < 64) {
        const __half2* row = reinterpret_cast<const __half2*>(&g_ft[2][b][tid][0]);
        float acc = 0.f;
#pragma unroll 8
        for (int p2 = 0; p2 < 64; p2++) {
            float2 v = __half22float2(row[p2]);
            acc += b3[2 * p2] * v.x + b3[2 * p2 + 1] * v.y;
        }
        g_cv[b][tid] = acc;
    }
}

__global__ void __launch_bounds__(256) stage2_kernel(
    const float* __restrict__ b1, const float* __restrict__ b3,
    float* __restrict__ out_move)
{
    extern __shared__ char s2[];
    const int bid = blockIdx.x;
    if (bid < 128)      sp_mma(s2, bid & 1, bid >> 1, b1);
    else if (bid < 192) move_mma(s2, bid - 128, out_move);
    else                g_mma(s2, bid - 192, b3);
}

// ============================================================================
// Main (hot): unchanged (bit-identical path).
// ============================================================================
__global__ void __launch_bounds__(256, 2) main_kernel(
    const float* __restrict__ b2, float* __restrict__ out_arrow)
{
    extern __shared__ char smc[];
    __shared__ float  s_cv[64];
    __shared__ float  s_b2[128];
    __shared__ __half s_dst[2][256];

    const uint32_t sb = smem_u32(smc);
    const int tid  = threadIdx.x;
    const int wid  = tid >> 5;
    const int lane = tid & 31;
    const int mt = blockIdx.x, b = blockIdx.y, m0 = mt * 2;

    const int ABUF = 65536;
    const int im = wid & 3;
    const int in = wid >> 2;

    const int rowinm = lane & 7, mi = lane >> 3;
    const int a_kx = mi >> 1;
    const int a_rl = ((mi & 1) << 3) + rowinm;
    const int b_rl = ((mi >> 1) << 3) + rowinm;
    const int b_sw = rowinm;
    const int b_kx = mi & 1;

    const int ag_grp  = tid & 7;
    const int ag_row0 = tid >> 3;

    {
        for (int i = tid; i < 4096; i += 256) {
            int o = i >> 5, grp = i & 31;
            int kc = grp >> 3, cgl = grp & 7;
            const uint4* src = reinterpret_cast<const uint4*>(g_w2h + o * 256 + grp * 8);
            uint32_t dst = (uint32_t)(kc * 16384 + o * 128 + ((cgl ^ (o & 7)) << 4));
            *reinterpret_cast<uint4*>(smc + dst) = *src;
        }
        if (tid < 64)  s_cv[tid] = g_cv[b][tid];
        if (tid < 128) s_b2[tid] = b2[tid];
        if (tid < 64) {
            int lm = tid >> 5, grp = tid & 31;
            *reinterpret_cast<uint4*>(&s_dst[lm][grp * 8]) =
                *reinterpret_cast<const uint4*>(&g_dstp_h[b][m0 + lm][grp * 8]);
        }
#pragma unroll
        for (int j = 0; j < 4; j++) {
            int row = ag_row0 + 32 * j;
            int n = row & 63, lm = row >> 6;
            uint4 s = *reinterpret_cast<const uint4*>(&g_srcp_h[b][n][ag_grp * 8]);
            uint4 d = *reinterpret_cast<const uint4*>(&g_dstp_h[b][m0 + lm][ag_grp * 8]);
            uint4 v = reluadd4(s, d);
            uint32_t off = (uint32_t)(row * 128 + ((ag_grp ^ (row & 7)) << 4));
            *reinterpret_cast<uint4*>(smc + ABUF + off) = v;
        }
    }
    __syncthreads();

    float c1[2][8][4];
#pragma unroll
    for (int m = 0; m < 2; m++)
#pragma unroll
        for (int i = 0; i < 8; i++)
#pragma unroll
            for (int j = 0; j < 4; j++) c1[m][i][j] = 0.f;

#pragma unroll 1
    for (int kc = 0; kc < 4; kc++) {
        const uint32_t curA = sb + (uint32_t)(ABUF + ((kc & 1) << 14));
        const uint32_t wHi  = sb + (uint32_t)(kc * 16384);

        uint4 ps[4];
        if (kc < 3) {
#pragma unroll
            for (int j = 0; j < 4; j++) {
                int row = ag_row0 + 32 * j;
                int n = row & 63;
                ps[j] = *reinterpret_cast<const uint4*>(
                    &g_srcp_h[b][n][(kc + 1) * 64 + ag_grp * 8]);
            }
        } else {
#pragma unroll
            for (int t = 0; t < 4; t++) {
                int i = tid + 256 * t;
                ps[t] = *reinterpret_cast<const uint4*>(
                    &g_Gh[b * 8192 + (i >> 4) * 128 + (i & 15) * 8]);
            }
        }

#pragma unroll
        for (int ks = 0; ks < 2; ks++) {
            uint32_t aH[2][4];
#pragma unroll
            for (int m = 0; m < 2; m++) {
                int a_r = im * 32 + m * 16 + a_rl;
                uint32_t co = (uint32_t)(((ks * 2 + a_kx) ^ (a_r & 7)) << 4);
                ldmx4(aH[m], curA + (uint32_t)(a_r * 128) + co);
            }
            uint32_t kco = (uint32_t)(((ks * 2 + b_kx) ^ b_sw) << 4);
            uint32_t bh[4][4];
#pragma unroll
            for (int q = 0; q < 4; q++) {
                int o_row = in * 64 + q * 16 + b_rl;
                ldmx4(bh[q], wHi + (uint32_t)(o_row * 128) + kco);
            }
#pragma unroll
            for (int q = 0; q < 4; q++)
#pragma unroll
                for (int m = 0; m < 2; m++) {
                    mma16816(c1[m][2 * q],     aH[m], bh[q][0], bh[q][1]);
                    mma16816(c1[m][2 * q + 1], aH[m], bh[q][2], bh[q][3]);
                }
        }

        uint4 pv[4];
        if (kc < 3) {
#pragma unroll
            for (int j = 0; j < 4; j++) {
                int row = ag_row0 + 32 * j;
                int lm = row >> 6;
                uint4 d = *reinterpret_cast<const uint4*>(
                    &s_dst[lm][(kc + 1) * 64 + ag_grp * 8]);
                pv[j] = reluadd4(ps[j], d);
            }
        } else {
#pragma unroll
            for (int t = 0; t < 4; t++) pv[t] = ps[t];
        }

#pragma unroll
        for (int ks = 2; ks < 4; ks++) {
            uint32_t aH[2][4];
#pragma unroll
            for (int m = 0; m < 2; m++) {
                int a_r = im * 32 + m * 16 + a_rl;
                uint32_t co = (uint32_t)(((ks * 2 + a_kx) ^ (a_r & 7)) << 4);
                ldmx4(aH[m], curA + (uint32_t)(a_r * 128) + co);
            }
            uint32_t kco = (uint32_t)(((ks * 2 + b_kx) ^ b_sw) << 4);
            uint32_t bh[4][4];
#pragma unroll
            for (int q = 0; q < 4; q++) {
                int o_row = in * 64 + q * 16 + b_rl;
                ldmx4(bh[q], wHi + (uint32_t)(o_row * 128) + kco);
            }
#pragma unroll
            for (int q = 0; q < 4; q++)
#pragma unroll
                for (int m = 0; m < 2; m++) {
                    mma16816(c1[m][2 * q],     aH[m], bh[q][0], bh[q][1]);
                    mma16816(c1[m][2 * q + 1], aH[m], bh[q][2], bh[q][3]);
                }
        }

        if (kc < 3) {
            char* obuf = smc + ABUF + (((kc + 1) & 1) << 14);
#pragma unroll
            for (int j = 0; j < 4; j++) {
                int row = ag_row0 + 32 * j;
                uint32_t off = (uint32_t)(row * 128 + ((ag_grp ^ (row & 7)) << 4));
                *reinterpret_cast<uint4*>(obuf + off) = pv[j];
            }
        } else {
#pragma unroll
            for (int t = 0; t < 4; t++) {
                int i = tid + 256 * t;
                int r = i >> 4, grp = i & 15;
                int kh = grp >> 3, cgl = grp & 7;
                uint32_t dst = (uint32_t)(ABUF + kh * 8192 + r * 128 +
                                          ((cgl ^ (r & 7)) << 4));
                *reinterpret_cast<uint4*>(smc + dst) = pv[t];
            }
        }
        __syncthreads();
    }

    const int ccol = (lane & 3) * 2;
    uint32_t aH2[2][4][4];
#pragma unroll
    for (int m = 0; m < 2; m++)
#pragma unroll
        for (int ko = 0; ko < 4; ko++) {
#pragma unroll
            for (int hn = 0; hn < 2; hn++) {
                int nt = 2 * ko + hn;
                float bv0 = s_b2[in * 64 + nt * 8 + ccol];
                float bv1 = s_b2[in * 64 + nt * 8 + ccol + 1];
                aH2[m][ko][hn * 2]     = packh2(fmaxf(c1[m][nt][0] + bv0, 0.f),
                                                fmaxf(c1[m][nt][1] + bv1, 0.f));
                aH2[m][ko][hn * 2 + 1] = packh2(fmaxf(c1[m][nt][2] + bv0, 0.f),
                                                fmaxf(c1[m][nt][3] + bv1, 0.f));
            }
        }

    float c2[2][8][4];
#pragma unroll
    for (int m = 0; m < 2; m++)
#pragma unroll
        for (int i = 0; i < 8; i++)
#pragma unroll
            for (int j = 0; j < 4; j++) c2[m][i][j] = 0.f;

    const uint32_t gBase = sb + (uint32_t)(ABUF + in * 8192);
#pragma unroll
    for (int ko = 0; ko < 4; ko++) {
        uint32_t kco = (uint32_t)(((ko * 2 + b_kx) ^ b_sw) << 4);
        uint32_t bh[4][4];
#pragma unroll
        for (int q = 0; q < 4; q++)
            ldmx4(bh[q], gBase + (uint32_t)((q * 16 + b_rl) * 128) + kco);
#pragma unroll
        for (int q = 0; q < 4; q++)
#pragma unroll
            for (int m = 0; m < 2; m++) {
                mma16816(c2[m][2 * q],     aH2[m][ko], bh[q][0], bh[q][1]);
                mma16816(c2[m][2 * q + 1], aH2[m][ko], bh[q][2], bh[q][3]);
            }
    }

    float* rbuf = reinterpret_cast<float*>(smc);
    if (in == 1) {
#pragma unroll
        for (int m = 0; m < 2; m++) {
            int r0 = im * 32 + m * 16 + (lane >> 2);
#pragma unroll
            for (int kt = 0; kt < 8; kt++) {
                int k = kt * 8 + ccol;
                *reinterpret_cast<float2*>(&rbuf[r0 * 72 + k]) =
                    make_float2(c2[m][kt][0], c2[m][kt][1]);
                *reinterpret_cast<float2*>(&rbuf[(r0 + 8) * 72 + k]) =
                    make_float2(c2[m][kt][2], c2[m][kt][3]);
            }
        }
    }
    __syncthreads();
    if (in == 0) {
#pragma unroll
        for (int m = 0; m < 2; m++) {
            int r0 = im * 32 + m * 16 + (lane >> 2);
            int r1 = r0 + 8;
            float* p0 = out_arrow + (((size_t)b * 4096 +
                                      (size_t)(r0 & 63) * 64 + m0 + (r0 >> 6)) << 6);
            float* p1 = out_arrow + (((size_t)b * 4096 +
                                      (size_t)(r1 & 63) * 64 + m0 + (r1 >> 6)) << 6);
#pragma unroll
            for (int kt = 0; kt < 8; kt++) {
                int k = kt * 8 + ccol;
                float2 q0 = *reinterpret_cast<const float2*>(&rbuf[r0 * 72 + k]);
                float2 q1 = *reinterpret_cast<const float2*>(&rbuf[r1 * 72 + k]);
                float cv0 = s_cv[k], cv1 = s_cv[k + 1];
                float2 v0 = make_float2((c2[m][kt][0] + q0.x + cv0) * SCALE_V,
                                        (c2[m][kt][1] + q0.y + cv1) * SCALE_V);
                float2 v1 = make_float2((c2[m][kt][2] + q1.x + cv0) * SCALE_V,
                                        (c2[m][kt][3] + q1.y + cv1) * SCALE_V);
                *reinterpret_cast<float2*>(p0 + k) = v0;
                *reinterpret_cast<float2*>(p1 + k) = v1;
            }
        }
    }
}

// ============================================================================
// launch
// ============================================================================
extern "C" void kernel_launch(void* const* d_in, const int* in_sizes, int n_in,
                              void* d_out, int out_size)
{
    (void)in_sizes; (void)n_in; (void)out_size;
    const float* x     = (const float*)d_in[0];
    const float* w_src = (const float*)d_in[1];
    const float* b_src = (const float*)d_in[2];
    const float* w_dst = (const float*)d_in[3];
    const float* b_dst = (const float*)d_in[4];
    const float* w_arr = (const float*)d_in[5];
    const float* b_arr = (const float*)d_in[6];
    const float* w1    = (const float*)d_in[7];
    const float* b1    = (const float*)d_in[8];
    const float* w2    = (const float*)d_in[9];
    const float* b2    = (const float*)d_in[10];
    const float* w3    = (const float*)d_in[11];
    const float* b3    = (const float*)d_in[12];

    float* out_move  = (float*)d_out;                       // 64*64*64
    float* out_arrow = (float*)d_out + 64 * 64 * 64;        // 64*4096*64

    constexpr int SMEM_MAIN = 98304;
    constexpr int SMEM_S2   = 81920;
    cudaFuncSetAttribute(main_kernel, cudaFuncAttributeMaxDynamicSharedMemorySize,
                         SMEM_MAIN);
    cudaFuncSetAttribute(stage2_kernel, cudaFuncAttributeMaxDynamicSharedMemorySize,
                         SMEM_S2);
    cudaFuncSetAttribute(prep_kernel, cudaFuncAttributeMaxDynamicSharedMemorySize,
                         SMEM_MAIN);

    prep_kernel<<<416, 256, SMEM_MAIN>>>(x, w_src, b_src, w_dst, b_dst,
                                         w_arr, b_arr, w1, w2, w3);
    stage2_kernel<<<256, 256, SMEM_S2>>>(b1, b3, out_move);
    main_kernel<<<dim3(32, 64), 256, SMEM_MAIN>>>(b2, out_arrow);
}